// round 12
// baseline (speedup 1.0000x reference)
#include <cuda_runtime.h>
#include <stdint.h>

#define N_NODES 50000
#define N_EDGES 400000
#define IN_FEAT 64
#define H_DIM 32
#define TILE_R 128

// ---- device scratch (no runtime allocation allowed) ----
__device__ float g_hWe[N_NODES * H_DIM];   // (relu(x@W0+b0)) @ W_edge
__device__ float g_out[N_NODES * H_DIM];   // h@Wr + bias, then += scatter(hWe)
__device__ float g_We[H_DIM * H_DIM];      // shared per-edge weight matrix

__device__ __forceinline__ void red_add_v4(float* addr, float4 v) {
    asm volatile("red.global.v4.f32.add [%0], {%1, %2, %3, %4};"
                 :: "l"(addr), "f"(v.x), "f"(v.y), "f"(v.z), "f"(v.w)
                 : "memory");
}
__device__ __forceinline__ float relu(float v) { return v > 0.f ? v : 0.f; }

// XOR swizzle for transposed smem tiles (k1 only).
__device__ __forceinline__ int swz(int k, int r) {
    return k * TILE_R + (r ^ (k & 28));
}

// ============================================================
// K0: W_edge = relu(nn_w1 + nn_b1) @ nn_w2 + nn_b2  (shared by all edges,
// since edge_attr == ones((E,1)))
// ============================================================
__global__ void k0_edge_weight(const float* __restrict__ nn_w1,
                               const float* __restrict__ nn_b1,
                               const float* __restrict__ nn_w2,
                               const float* __restrict__ nn_b2) {
    __shared__ float w1[H_DIM];
    int t = threadIdx.x;
    if (t < H_DIM) w1[t] = relu(nn_w1[t] + nn_b1[t]);
    __syncthreads();
    for (int i = t; i < H_DIM * H_DIM; i += blockDim.x) {
        float acc = nn_b2[i];
        #pragma unroll
        for (int k = 0; k < H_DIM; k++)
            acc += w1[k] * nn_w2[k * (H_DIM * H_DIM) + i];
        g_We[i] = acc;
    }
}

// ============================================================
// K1 (fused): h = relu(x@W0 + b0)  [smem only]
//             g_hWe = h @ W_edge
//             g_out = h @ conv_root + conv_bias   (scatter target init)
// Register-tiled 4x4 micro-tiles, 256 threads, 128-row tiles.
// ============================================================
__global__ void __launch_bounds__(256) k1_fused(
        const float* __restrict__ x,
        const float* __restrict__ lin0_w,
        const float* __restrict__ lin0_b,
        const float* __restrict__ conv_root,
        const float* __restrict__ conv_bias,
        int n_nodes) {
    __shared__ float pool[IN_FEAT * TILE_R];   // 32 KB: xT, then hT
    __shared__ float4 sw0[IN_FEAT * 8];        // 8 KB
    __shared__ float4 sWe[H_DIM * 8];          // 4 KB
    __shared__ float4 sWr[H_DIM * 8];          // 4 KB

    int tid  = threadIdx.x;
    int tx   = tid & 7;
    int ty   = tid >> 3;
    int row0 = blockIdx.x * TILE_R;
    int rb   = ty * 4;

    sw0[tid]       = ((const float4*)lin0_w)[tid];
    sw0[tid + 256] = ((const float4*)lin0_w)[tid + 256];
    sWe[tid]       = ((const float4*)g_We)[tid];
    sWr[tid]       = ((const float4*)conv_root)[tid];
    float4 b0 = __ldg((const float4*)lin0_b + tx);
    float4 bc = __ldg((const float4*)conv_bias + tx);

    // stage x tile transposed: 128 rows x 16 float4 = 2048 f4, 8 per thread
    #pragma unroll
    for (int it = 0; it < 8; it++) {
        int m = tid + 256 * it;
        int r = m >> 4, q = m & 15;
        float4 v = make_float4(0.f, 0.f, 0.f, 0.f);
        if (row0 + r < n_nodes)
            v = __ldg((const float4*)(x + (size_t)(row0 + r) * IN_FEAT) + q);
        pool[swz(4 * q + 0, r)] = v.x;
        pool[swz(4 * q + 1, r)] = v.y;
        pool[swz(4 * q + 2, r)] = v.z;
        pool[swz(4 * q + 3, r)] = v.w;
    }
    __syncthreads();

    // ---- stage 1: h micro-tile (4 rows x 4 cols) ----
    float4 a0 = b0, a1 = b0, a2 = b0, a3 = b0;
    #pragma unroll 8
    for (int k = 0; k < IN_FEAT; k++) {
        float4 xv = *(const float4*)&pool[swz(k, rb)];
        float4 wv = sw0[k * 8 + tx];
        a0.x = fmaf(xv.x, wv.x, a0.x); a0.y = fmaf(xv.x, wv.y, a0.y);
        a0.z = fmaf(xv.x, wv.z, a0.z); a0.w = fmaf(xv.x, wv.w, a0.w);
        a1.x = fmaf(xv.y, wv.x, a1.x); a1.y = fmaf(xv.y, wv.y, a1.y);
        a1.z = fmaf(xv.y, wv.z, a1.z); a1.w = fmaf(xv.y, wv.w, a1.w);
        a2.x = fmaf(xv.z, wv.x, a2.x); a2.y = fmaf(xv.z, wv.y, a2.y);
        a2.z = fmaf(xv.z, wv.z, a2.z); a2.w = fmaf(xv.z, wv.w, a2.w);
        a3.x = fmaf(xv.w, wv.x, a3.x); a3.y = fmaf(xv.w, wv.y, a3.y);
        a3.z = fmaf(xv.w, wv.z, a3.z); a3.w = fmaf(xv.w, wv.w, a3.w);
    }
    __syncthreads();  // all xT reads complete before pool is reused

    {
        float4 rr[4] = {a0, a1, a2, a3};
        #pragma unroll
        for (int j = 0; j < 4; j++) {
            int r = rb + j;
            pool[swz(4 * tx + 0, r)] = relu(rr[j].x);
            pool[swz(4 * tx + 1, r)] = relu(rr[j].y);
            pool[swz(4 * tx + 2, r)] = relu(rr[j].z);
            pool[swz(4 * tx + 3, r)] = relu(rr[j].w);
        }
    }
    __syncthreads();

    // ---- stage 2: hWe = h@We (no bias), out = h@Wr + conv_bias ----
    float4 e0 = make_float4(0.f, 0.f, 0.f, 0.f), e1 = e0, e2 = e0, e3 = e0;
    float4 o0 = bc, o1 = bc, o2 = bc, o3 = bc;
    #pragma unroll 8
    for (int k = 0; k < H_DIM; k++) {
        float4 hv = *(const float4*)&pool[swz(k, rb)];
        float4 we = sWe[k * 8 + tx];
        float4 wr = sWr[k * 8 + tx];
        e0.x = fmaf(hv.x, we.x, e0.x); e0.y = fmaf(hv.x, we.y, e0.y);
        e0.z = fmaf(hv.x, we.z, e0.z); e0.w = fmaf(hv.x, we.w, e0.w);
        e1.x = fmaf(hv.y, we.x, e1.x); e1.y = fmaf(hv.y, we.y, e1.y);
        e1.z = fmaf(hv.y, we.z, e1.z); e1.w = fmaf(hv.y, we.w, e1.w);
        e2.x = fmaf(hv.z, we.x, e2.x); e2.y = fmaf(hv.z, we.y, e2.y);
        e2.z = fmaf(hv.z, we.z, e2.z); e2.w = fmaf(hv.z, we.w, e2.w);
        e3.x = fmaf(hv.w, we.x, e3.x); e3.y = fmaf(hv.w, we.y, e3.y);
        e3.z = fmaf(hv.w, we.z, e3.z); e3.w = fmaf(hv.w, we.w, e3.w);
        o0.x = fmaf(hv.x, wr.x, o0.x); o0.y = fmaf(hv.x, wr.y, o0.y);
        o0.z = fmaf(hv.x, wr.z, o0.z); o0.w = fmaf(hv.x, wr.w, o0.w);
        o1.x = fmaf(hv.y, wr.x, o1.x); o1.y = fmaf(hv.y, wr.y, o1.y);
        o1.z = fmaf(hv.y, wr.z, o1.z); o1.w = fmaf(hv.y, wr.w, o1.w);
        o2.x = fmaf(hv.z, wr.x, o2.x); o2.y = fmaf(hv.z, wr.y, o2.y);
        o2.z = fmaf(hv.z, wr.z, o2.z); o2.w = fmaf(hv.z, wr.w, o2.w);
        o3.x = fmaf(hv.w, wr.x, o3.x); o3.y = fmaf(hv.w, wr.y, o3.y);
        o3.z = fmaf(hv.w, wr.z, o3.z); o3.w = fmaf(hv.w, wr.w, o3.w);
    }

    float4 eres[4] = {e0, e1, e2, e3};
    float4 ores[4] = {o0, o1, o2, o3};
    #pragma unroll
    for (int i = 0; i < 4; i++) {
        int gr = row0 + rb + i;
        if (gr < n_nodes) {
            *(float4*)(g_hWe + (size_t)gr * H_DIM + tx * 4) = eres[i];
            *(float4*)(g_out + (size_t)gr * H_DIM + tx * 4) = ores[i];
        }
    }
}

// ============================================================
// K2: out[dst] += hWe[src]  — vector atomics. 8 threads per edge, each
// handles one float4 quarter via red.global.v4.f32.add.
// ============================================================
__global__ void k2_scatter(const int* __restrict__ edge_index, int n_edges) {
    long long tid = (long long)blockIdx.x * blockDim.x + threadIdx.x;
    int e = (int)(tid >> 3);
    if (e >= n_edges) return;
    int q = (int)(tid & 7);

    int src = __ldg(&edge_index[e]);            // edge_index[0][e]
    int dst = __ldg(&edge_index[n_edges + e]);  // edge_index[1][e]

    float4 v = __ldg((const float4*)(g_hWe + (size_t)src * H_DIM) + q);
    red_add_v4(g_out + (size_t)dst * H_DIM + q * 4, v);
}

// ============================================================
// K4: per-edge score, 8 lanes per edge, register-only.
// Lane l: loads quarter l of out[src], out[dst]; p = a*b (4 vals);
// holds W1 rows 4l..4l+3 in 8 float4 regs; partial v[j] = sum_i p[i]*W1[..][j].
// Shuffle reduce-scatter (xor 4,2,1) leaves lane l with acc[l];
// relu + *W2[l], butterfly-sum, lane 0 writes score.
// No smem staging -> occupancy not smem-bound; huge MLP from 3.2M threads.
// ============================================================
__global__ void __launch_bounds__(256) k4_score(
        const int* __restrict__ edge_index,
        const float* __restrict__ lin1_w,
        const float* __restrict__ lin1_b,
        const float* __restrict__ lin2_w,
        const float* __restrict__ lin2_b,
        float* __restrict__ out_score,
        int n_edges) {
    long long gid = (long long)blockIdx.x * blockDim.x + threadIdx.x;
    int e = (int)(gid >> 3);
    if (e >= n_edges) return;          // whole 8-lane group exits together
    int l = (int)(gid & 7);

    // W1 slice: rows 4l..4l+3 (8 float4), once per thread
    const float4* W1 = (const float4*)lin1_w;
    float4 wA0 = __ldg(&W1[(4 * l + 0) * 2]);
    float4 wB0 = __ldg(&W1[(4 * l + 0) * 2 + 1]);
    float4 wA1 = __ldg(&W1[(4 * l + 1) * 2]);
    float4 wB1 = __ldg(&W1[(4 * l + 1) * 2 + 1]);
    float4 wA2 = __ldg(&W1[(4 * l + 2) * 2]);
    float4 wB2 = __ldg(&W1[(4 * l + 2) * 2 + 1]);
    float4 wA3 = __ldg(&W1[(4 * l + 3) * 2]);
    float4 wB3 = __ldg(&W1[(4 * l + 3) * 2 + 1]);
    float b1l = __ldg(&lin1_b[l]);
    float w2l = __ldg(&lin2_w[l]);

    int src = __ldg(&edge_index[e]);
    int dst = __ldg(&edge_index[n_edges + e]);

    float4 a = __ldg((const float4*)(g_out + (size_t)src * H_DIM) + l);
    float4 b = __ldg((const float4*)(g_out + (size_t)dst * H_DIM) + l);
    float p0 = a.x * b.x, p1 = a.y * b.y, p2 = a.z * b.z, p3 = a.w * b.w;

    // partials v[j] for j = 0..7 over this lane's 4 k-values
    float v0, v1, v2, v3, v4, v5, v6, v7;
    v0 = fmaf(p0, wA0.x, fmaf(p1, wA1.x, fmaf(p2, wA2.x, p3 * wA3.x)));
    v1 = fmaf(p0, wA0.y, fmaf(p1, wA1.y, fmaf(p2, wA2.y, p3 * wA3.y)));
    v2 = fmaf(p0, wA0.z, fmaf(p1, wA1.z, fmaf(p2, wA2.z, p3 * wA3.z)));
    v3 = fmaf(p0, wA0.w, fmaf(p1, wA1.w, fmaf(p2, wA2.w, p3 * wA3.w)));
    v4 = fmaf(p0, wB0.x, fmaf(p1, wB1.x, fmaf(p2, wB2.x, p3 * wB3.x)));
    v5 = fmaf(p0, wB0.y, fmaf(p1, wB1.y, fmaf(p2, wB2.y, p3 * wB3.y)));
    v6 = fmaf(p0, wB0.z, fmaf(p1, wB1.z, fmaf(p2, wB2.z, p3 * wB3.z)));
    v7 = fmaf(p0, wB0.w, fmaf(p1, wB1.w, fmaf(p2, wB2.w, p3 * wB3.w)));

    const unsigned FULL = 0xFFFFFFFFu;
    // reduce-scatter step 1 (xor 4): keep the half matching (l&4)
    bool hi4 = (l & 4) != 0;
    float s0 = hi4 ? v0 : v4, s1 = hi4 ? v1 : v5;
    float s2 = hi4 ? v2 : v6, s3 = hi4 ? v3 : v7;
    float k0 = hi4 ? v4 : v0, k1 = hi4 ? v5 : v1;
    float k2 = hi4 ? v6 : v2, k3 = hi4 ? v7 : v3;
    float u0 = k0 + __shfl_xor_sync(FULL, s0, 4);
    float u1 = k1 + __shfl_xor_sync(FULL, s1, 4);
    float u2 = k2 + __shfl_xor_sync(FULL, s2, 4);
    float u3 = k3 + __shfl_xor_sync(FULL, s3, 4);
    // step 2 (xor 2)
    bool hi2 = (l & 2) != 0;
    float t0 = hi2 ? u0 : u2, t1 = hi2 ? u1 : u3;
    float q0 = hi2 ? u2 : u0, q1 = hi2 ? u3 : u1;
    float r0 = q0 + __shfl_xor_sync(FULL, t0, 2);
    float r1 = q1 + __shfl_xor_sync(FULL, t1, 2);
    // step 3 (xor 1)
    bool hi1 = (l & 1) != 0;
    float snd = hi1 ? r0 : r1;
    float kp  = hi1 ? r1 : r0;
    float acc = kp + __shfl_xor_sync(FULL, snd, 1);   // = acc[l]

    // score
    float t = relu(acc + b1l) * w2l;
    t += __shfl_xor_sync(FULL, t, 1);
    t += __shfl_xor_sync(FULL, t, 2);
    t += __shfl_xor_sync(FULL, t, 4);
    if (l == 0)
        out_score[e] = t + __ldg(&lin2_b[0]);
}

// ============================================================
// launch
// ============================================================
extern "C" void kernel_launch(void* const* d_in, const int* in_sizes, int n_in,
                              void* d_out, int out_size) {
    const float* x          = (const float*)d_in[0];
    const int*   edge_index = (const int*)d_in[1];   // int64 in JAX -> int32 in harness
    const float* lin0_w     = (const float*)d_in[2];
    const float* lin0_b     = (const float*)d_in[3];
    const float* nn_w1      = (const float*)d_in[4];
    const float* nn_b1      = (const float*)d_in[5];
    const float* nn_w2      = (const float*)d_in[6];
    const float* nn_b2      = (const float*)d_in[7];
    const float* conv_root  = (const float*)d_in[8];
    const float* conv_bias  = (const float*)d_in[9];
    const float* lin1_w     = (const float*)d_in[10];
    const float* lin1_b     = (const float*)d_in[11];
    const float* lin2_w     = (const float*)d_in[12];
    const float* lin2_b     = (const float*)d_in[13];
    float* out_score = (float*)d_out;

    int n_nodes = in_sizes[0] / IN_FEAT;
    int n_edges = in_sizes[1] / 2;

    // K0: shared edge weight matrix (tiny)
    k0_edge_weight<<<1, 256>>>(nn_w1, nn_b1, nn_w2, nn_b2);

    // K1 fused: h (smem-only) -> g_hWe and g_out init
    {
        int blocks = (n_nodes + TILE_R - 1) / TILE_R;
        k1_fused<<<blocks, 256>>>(x, lin0_w, lin0_b, conv_root, conv_bias,
                                  n_nodes);
    }

    // K2: 8 threads per edge, float4 reductions into g_out
    {
        long long total = (long long)n_edges * 8;
        int blocks = (int)((total + 255) / 256);
        k2_scatter<<<blocks, 256>>>(edge_index, n_edges);
    }

    // K4: 8 lanes per edge, register-only
    {
        long long total = (long long)n_edges * 8;
        int blocks = (int)((total + 255) / 256);
        k4_score<<<blocks, 256>>>(edge_index, lin1_w, lin1_b, lin2_w, lin2_b,
                                  out_score, n_edges);
    }
}

// round 13
// speedup vs baseline: 2.5749x; 2.5749x over previous
#include <cuda_runtime.h>
#include <stdint.h>

#define N_NODES 50000
#define N_EDGES 400000
#define IN_FEAT 64
#define H_DIM 32
#define TILE_R 128
#define PSTR 36   // padded smem stride per edge (32 + 4)

// ---- device scratch (no runtime allocation allowed) ----
__device__ float g_hWe[N_NODES * H_DIM];   // (relu(x@W0+b0)) @ W_edge
__device__ float g_out[N_NODES * H_DIM];   // h@Wr + bias, then += scatter(hWe)
__device__ float g_We[H_DIM * H_DIM];      // shared per-edge weight matrix

__device__ __forceinline__ void red_add_v4(float* addr, float4 v) {
    asm volatile("red.global.v4.f32.add [%0], {%1, %2, %3, %4};"
                 :: "l"(addr), "f"(v.x), "f"(v.y), "f"(v.z), "f"(v.w)
                 : "memory");
}
__device__ __forceinline__ float relu(float v) { return v > 0.f ? v : 0.f; }

// XOR swizzle for transposed smem tiles (k1 only).
__device__ __forceinline__ int swz(int k, int r) {
    return k * TILE_R + (r ^ (k & 28));
}

// ============================================================
// K0: W_edge = relu(nn_w1 + nn_b1) @ nn_w2 + nn_b2  (shared by all edges,
// since edge_attr == ones((E,1)))
// ============================================================
__global__ void k0_edge_weight(const float* __restrict__ nn_w1,
                               const float* __restrict__ nn_b1,
                               const float* __restrict__ nn_w2,
                               const float* __restrict__ nn_b2) {
    __shared__ float w1[H_DIM];
    int t = threadIdx.x;
    if (t < H_DIM) w1[t] = relu(nn_w1[t] + nn_b1[t]);
    __syncthreads();
    for (int i = t; i < H_DIM * H_DIM; i += blockDim.x) {
        float acc = nn_b2[i];
        #pragma unroll
        for (int k = 0; k < H_DIM; k++)
            acc += w1[k] * nn_w2[k * (H_DIM * H_DIM) + i];
        g_We[i] = acc;
    }
}

// ============================================================
// K1 (fused): h = relu(x@W0 + b0)  [smem only]
//             g_hWe = h @ W_edge
//             g_out = h @ conv_root + conv_bias   (scatter target init)
// Register-tiled 4x4 micro-tiles, 256 threads, 128-row tiles.
// ============================================================
__global__ void __launch_bounds__(256) k1_fused(
        const float* __restrict__ x,
        const float* __restrict__ lin0_w,
        const float* __restrict__ lin0_b,
        const float* __restrict__ conv_root,
        const float* __restrict__ conv_bias,
        int n_nodes) {
    __shared__ float pool[IN_FEAT * TILE_R];   // 32 KB: xT, then hT
    __shared__ float4 sw0[IN_FEAT * 8];        // 8 KB
    __shared__ float4 sWe[H_DIM * 8];          // 4 KB
    __shared__ float4 sWr[H_DIM * 8];          // 4 KB

    int tid  = threadIdx.x;
    int tx   = tid & 7;
    int ty   = tid >> 3;
    int row0 = blockIdx.x * TILE_R;
    int rb   = ty * 4;

    sw0[tid]       = ((const float4*)lin0_w)[tid];
    sw0[tid + 256] = ((const float4*)lin0_w)[tid + 256];
    sWe[tid]       = ((const float4*)g_We)[tid];
    sWr[tid]       = ((const float4*)conv_root)[tid];
    float4 b0 = __ldg((const float4*)lin0_b + tx);
    float4 bc = __ldg((const float4*)conv_bias + tx);

    // stage x tile transposed: 128 rows x 16 float4 = 2048 f4, 8 per thread
    #pragma unroll
    for (int it = 0; it < 8; it++) {
        int m = tid + 256 * it;
        int r = m >> 4, q = m & 15;
        float4 v = make_float4(0.f, 0.f, 0.f, 0.f);
        if (row0 + r < n_nodes)
            v = __ldg((const float4*)(x + (size_t)(row0 + r) * IN_FEAT) + q);
        pool[swz(4 * q + 0, r)] = v.x;
        pool[swz(4 * q + 1, r)] = v.y;
        pool[swz(4 * q + 2, r)] = v.z;
        pool[swz(4 * q + 3, r)] = v.w;
    }
    __syncthreads();

    // ---- stage 1: h micro-tile (4 rows x 4 cols) ----
    float4 a0 = b0, a1 = b0, a2 = b0, a3 = b0;
    #pragma unroll 8
    for (int k = 0; k < IN_FEAT; k++) {
        float4 xv = *(const float4*)&pool[swz(k, rb)];
        float4 wv = sw0[k * 8 + tx];
        a0.x = fmaf(xv.x, wv.x, a0.x); a0.y = fmaf(xv.x, wv.y, a0.y);
        a0.z = fmaf(xv.x, wv.z, a0.z); a0.w = fmaf(xv.x, wv.w, a0.w);
        a1.x = fmaf(xv.y, wv.x, a1.x); a1.y = fmaf(xv.y, wv.y, a1.y);
        a1.z = fmaf(xv.y, wv.z, a1.z); a1.w = fmaf(xv.y, wv.w, a1.w);
        a2.x = fmaf(xv.z, wv.x, a2.x); a2.y = fmaf(xv.z, wv.y, a2.y);
        a2.z = fmaf(xv.z, wv.z, a2.z); a2.w = fmaf(xv.z, wv.w, a2.w);
        a3.x = fmaf(xv.w, wv.x, a3.x); a3.y = fmaf(xv.w, wv.y, a3.y);
        a3.z = fmaf(xv.w, wv.z, a3.z); a3.w = fmaf(xv.w, wv.w, a3.w);
    }
    __syncthreads();  // all xT reads complete before pool is reused

    {
        float4 rr[4] = {a0, a1, a2, a3};
        #pragma unroll
        for (int j = 0; j < 4; j++) {
            int r = rb + j;
            pool[swz(4 * tx + 0, r)] = relu(rr[j].x);
            pool[swz(4 * tx + 1, r)] = relu(rr[j].y);
            pool[swz(4 * tx + 2, r)] = relu(rr[j].z);
            pool[swz(4 * tx + 3, r)] = relu(rr[j].w);
        }
    }
    __syncthreads();

    // ---- stage 2: hWe = h@We (no bias), out = h@Wr + conv_bias ----
    float4 e0 = make_float4(0.f, 0.f, 0.f, 0.f), e1 = e0, e2 = e0, e3 = e0;
    float4 o0 = bc, o1 = bc, o2 = bc, o3 = bc;
    #pragma unroll 8
    for (int k = 0; k < H_DIM; k++) {
        float4 hv = *(const float4*)&pool[swz(k, rb)];
        float4 we = sWe[k * 8 + tx];
        float4 wr = sWr[k * 8 + tx];
        e0.x = fmaf(hv.x, we.x, e0.x); e0.y = fmaf(hv.x, we.y, e0.y);
        e0.z = fmaf(hv.x, we.z, e0.z); e0.w = fmaf(hv.x, we.w, e0.w);
        e1.x = fmaf(hv.y, we.x, e1.x); e1.y = fmaf(hv.y, we.y, e1.y);
        e1.z = fmaf(hv.y, we.z, e1.z); e1.w = fmaf(hv.y, we.w, e1.w);
        e2.x = fmaf(hv.z, we.x, e2.x); e2.y = fmaf(hv.z, we.y, e2.y);
        e2.z = fmaf(hv.z, we.z, e2.z); e2.w = fmaf(hv.z, we.w, e2.w);
        e3.x = fmaf(hv.w, we.x, e3.x); e3.y = fmaf(hv.w, we.y, e3.y);
        e3.z = fmaf(hv.w, we.z, e3.z); e3.w = fmaf(hv.w, we.w, e3.w);
        o0.x = fmaf(hv.x, wr.x, o0.x); o0.y = fmaf(hv.x, wr.y, o0.y);
        o0.z = fmaf(hv.x, wr.z, o0.z); o0.w = fmaf(hv.x, wr.w, o0.w);
        o1.x = fmaf(hv.y, wr.x, o1.x); o1.y = fmaf(hv.y, wr.y, o1.y);
        o1.z = fmaf(hv.y, wr.z, o1.z); o1.w = fmaf(hv.y, wr.w, o1.w);
        o2.x = fmaf(hv.z, wr.x, o2.x); o2.y = fmaf(hv.z, wr.y, o2.y);
        o2.z = fmaf(hv.z, wr.z, o2.z); o2.w = fmaf(hv.z, wr.w, o2.w);
        o3.x = fmaf(hv.w, wr.x, o3.x); o3.y = fmaf(hv.w, wr.y, o3.y);
        o3.z = fmaf(hv.w, wr.z, o3.z); o3.w = fmaf(hv.w, wr.w, o3.w);
    }

    float4 eres[4] = {e0, e1, e2, e3};
    float4 ores[4] = {o0, o1, o2, o3};
    #pragma unroll
    for (int i = 0; i < 4; i++) {
        int gr = row0 + rb + i;
        if (gr < n_nodes) {
            *(float4*)(g_hWe + (size_t)gr * H_DIM + tx * 4) = eres[i];
            *(float4*)(g_out + (size_t)gr * H_DIM + tx * 4) = ores[i];
        }
    }
}

// ============================================================
// K2: out[dst] += hWe[src]  — vector atomics. 8 threads per edge, each
// handles one float4 quarter via red.global.v4.f32.add.
// ============================================================
__global__ void k2_scatter(const int* __restrict__ edge_index, int n_edges) {
    long long tid = (long long)blockIdx.x * blockDim.x + threadIdx.x;
    int e = (int)(tid >> 3);
    if (e >= n_edges) return;
    int q = (int)(tid & 7);

    int src = __ldg(&edge_index[e]);            // edge_index[0][e]
    int dst = __ldg(&edge_index[n_edges + e]);  // edge_index[1][e]

    float4 v = __ldg((const float4*)(g_hWe + (size_t)src * H_DIM) + q);
    red_add_v4(g_out + (size_t)dst * H_DIM + q * 4, v);
}

// ============================================================
// K4: per-edge score, warp-autonomous two-phase.
// Each warp owns 32 edges and a private padded smem slice; no block-wide
// barrier between phases (only __syncwarp), so warps overlap freely.
// Phase A: lane i holds edge i's (src,dst); 8 passes x (shfl idx, 8-lane
//          coalesced row gathers, p = a*b, STS.128 to padded slice).
// Phase B: thread-per-edge; p read chunk-wise (LDS.128), weights via
//          broadcast LDS from block-shared sW1.
// ============================================================
__global__ void __launch_bounds__(256) k4_score(
        const int* __restrict__ edge_index,
        const float* __restrict__ lin1_w,
        const float* __restrict__ lin1_b,
        const float* __restrict__ lin2_w,
        const float* __restrict__ lin2_b,
        float* __restrict__ out_score,
        int n_edges) {
    __shared__ float pT[8][32 * PSTR];        // 36.9 KB: per-warp slices
    __shared__ float sW1[H_DIM * 8];          // row-major [k][j], 1 KB
    __shared__ float sB1[8], sW2[8];
    __shared__ float sB2;

    int tid  = threadIdx.x;
    int wid  = tid >> 5;
    int lane = tid & 31;

    if (tid < H_DIM * 8) sW1[tid] = lin1_w[tid];
    if (tid < 8) { sB1[tid] = lin1_b[tid]; sW2[tid] = lin2_w[tid]; }
    if (tid == 0) sB2 = lin2_b[0];
    __syncthreads();   // weights visible to all warps (once per block)

    const unsigned FULL = 0xFFFFFFFFu;
    int base = (blockIdx.x * 8 + wid) * 32;   // this warp's 32-edge tile
    int mye  = base + lane;
    int msrc = 0, mdst = 0;
    if (mye < n_edges) {
        msrc = __ldg(&edge_index[mye]);
        mdst = __ldg(&edge_index[n_edges + mye]);
    }

    float* P = &pT[wid][0];

    // Phase A: 8 passes; pass p covers edges 4p..4p+3 (lane>>3 selects edge,
    // lane&7 selects float4 quarter -> 8-lane coalesced row gathers).
    #pragma unroll
    for (int ps = 0; ps < 8; ps++) {
        int el = ps * 4 + (lane >> 3);
        int q  = lane & 7;
        int s  = __shfl_sync(FULL, msrc, el);
        int d  = __shfl_sync(FULL, mdst, el);
        float4 a = __ldg((const float4*)(g_out + (size_t)s * H_DIM) + q);
        float4 b = __ldg((const float4*)(g_out + (size_t)d * H_DIM) + q);
        float4 pv = make_float4(a.x * b.x, a.y * b.y, a.z * b.z, a.w * b.w);
        *(float4*)&P[el * PSTR + 4 * q] = pv;
    }
    __syncwarp();

    // Phase B: lane = edge (base+lane). p read 4-at-a-time from smem.
    float acc0 = sB1[0], acc1 = sB1[1], acc2 = sB1[2], acc3 = sB1[3];
    float acc4 = sB1[4], acc5 = sB1[5], acc6 = sB1[6], acc7 = sB1[7];
    #pragma unroll
    for (int q = 0; q < 8; q++) {
        float4 pv = *(const float4*)&P[lane * PSTR + 4 * q];
        #pragma unroll
        for (int i = 0; i < 4; i++) {
            int k = 4 * q + i;
            float pk = (i == 0) ? pv.x : (i == 1) ? pv.y : (i == 2) ? pv.z : pv.w;
            float4 w0 = *(const float4*)&sW1[k * 8];      // broadcast
            float4 w1 = *(const float4*)&sW1[k * 8 + 4];  // broadcast
            acc0 = fmaf(pk, w0.x, acc0); acc1 = fmaf(pk, w0.y, acc1);
            acc2 = fmaf(pk, w0.z, acc2); acc3 = fmaf(pk, w0.w, acc3);
            acc4 = fmaf(pk, w1.x, acc4); acc5 = fmaf(pk, w1.y, acc5);
            acc6 = fmaf(pk, w1.z, acc6); acc7 = fmaf(pk, w1.w, acc7);
        }
    }

    float score = sB2;
    score = fmaf(relu(acc0), sW2[0], score);
    score = fmaf(relu(acc1), sW2[1], score);
    score = fmaf(relu(acc2), sW2[2], score);
    score = fmaf(relu(acc3), sW2[3], score);
    score = fmaf(relu(acc4), sW2[4], score);
    score = fmaf(relu(acc5), sW2[5], score);
    score = fmaf(relu(acc6), sW2[6], score);
    score = fmaf(relu(acc7), sW2[7], score);

    if (mye < n_edges) out_score[mye] = score;   // coalesced STG.32
}

// ============================================================
// launch
// ============================================================
extern "C" void kernel_launch(void* const* d_in, const int* in_sizes, int n_in,
                              void* d_out, int out_size) {
    const float* x          = (const float*)d_in[0];
    const int*   edge_index = (const int*)d_in[1];   // int64 in JAX -> int32 in harness
    const float* lin0_w     = (const float*)d_in[2];
    const float* lin0_b     = (const float*)d_in[3];
    const float* nn_w1      = (const float*)d_in[4];
    const float* nn_b1      = (const float*)d_in[5];
    const float* nn_w2      = (const float*)d_in[6];
    const float* nn_b2      = (const float*)d_in[7];
    const float* conv_root  = (const float*)d_in[8];
    const float* conv_bias  = (const float*)d_in[9];
    const float* lin1_w     = (const float*)d_in[10];
    const float* lin1_b     = (const float*)d_in[11];
    const float* lin2_w     = (const float*)d_in[12];
    const float* lin2_b     = (const float*)d_in[13];
    float* out_score = (float*)d_out;

    int n_nodes = in_sizes[0] / IN_FEAT;
    int n_edges = in_sizes[1] / 2;

    // K0: shared edge weight matrix (tiny)
    k0_edge_weight<<<1, 256>>>(nn_w1, nn_b1, nn_w2, nn_b2);

    // K1 fused: h (smem-only) -> g_hWe and g_out init
    {
        int blocks = (n_nodes + TILE_R - 1) / TILE_R;
        k1_fused<<<blocks, 256>>>(x, lin0_w, lin0_b, conv_root, conv_bias,
                                  n_nodes);
    }

    // K2: 8 threads per edge, float4 reductions into g_out
    {
        long long total = (long long)n_edges * 8;
        int blocks = (int)((total + 255) / 256);
        k2_scatter<<<blocks, 256>>>(edge_index, n_edges);
    }

    // K4: warp-autonomous, 32 edges per warp (8 warps per block)
    {
        int warps = (n_edges + 31) / 32;
        int blocks = (warps + 7) / 8;
        k4_score<<<blocks, 256>>>(edge_index, lin1_w, lin1_b, lin2_w, lin2_b,
                                  out_score, n_edges);
    }
}

// round 16
// speedup vs baseline: 2.6026x; 1.0108x over previous
#include <cuda_runtime.h>
#include <stdint.h>

#define N_NODES 50000
#define N_EDGES 400000
#define IN_FEAT 64
#define H_DIM 32
#define TILE_R 128

// ---- device scratch (no runtime allocation allowed) ----
__device__ float g_hWe[N_NODES * H_DIM];   // (relu(x@W0+b0)) @ W_edge
__device__ float g_out[N_NODES * H_DIM];   // h@Wr + bias, then += scatter(hWe)
__device__ float g_We[H_DIM * H_DIM];      // shared per-edge weight matrix

__device__ __forceinline__ void red_add_v4(float* addr, float4 v) {
    asm volatile("red.global.v4.f32.add [%0], {%1, %2, %3, %4};"
                 :: "l"(addr), "f"(v.x), "f"(v.y), "f"(v.z), "f"(v.w)
                 : "memory");
}
__device__ __forceinline__ float relu(float v) { return v > 0.f ? v : 0.f; }

// XOR swizzle for transposed smem tiles (k1 only).
__device__ __forceinline__ int swz(int k, int r) {
    return k * TILE_R + (r ^ (k & 28));
}

// ============================================================
// K0: W_edge = relu(nn_w1 + nn_b1) @ nn_w2 + nn_b2  (shared by all edges,
// since edge_attr == ones((E,1)))
// ============================================================
__global__ void k0_edge_weight(const float* __restrict__ nn_w1,
                               const float* __restrict__ nn_b1,
                               const float* __restrict__ nn_w2,
                               const float* __restrict__ nn_b2) {
    __shared__ float w1[H_DIM];
    int t = threadIdx.x;
    if (t < H_DIM) w1[t] = relu(nn_w1[t] + nn_b1[t]);
    __syncthreads();
    for (int i = t; i < H_DIM * H_DIM; i += blockDim.x) {
        float acc = nn_b2[i];
        #pragma unroll
        for (int k = 0; k < H_DIM; k++)
            acc += w1[k] * nn_w2[k * (H_DIM * H_DIM) + i];
        g_We[i] = acc;
    }
}

// ============================================================
// K1 (fused): h = relu(x@W0 + b0)  [smem only]
//             g_hWe = h @ W_edge
//             g_out = h @ conv_root + conv_bias   (scatter target init)
// Register-tiled 4x4 micro-tiles, 256 threads, 128-row tiles.
// ============================================================
__global__ void __launch_bounds__(256) k1_fused(
        const float* __restrict__ x,
        const float* __restrict__ lin0_w,
        const float* __restrict__ lin0_b,
        const float* __restrict__ conv_root,
        const float* __restrict__ conv_bias,
        int n_nodes) {
    __shared__ float pool[IN_FEAT * TILE_R];   // 32 KB: xT, then hT
    __shared__ float4 sw0[IN_FEAT * 8];        // 8 KB
    __shared__ float4 sWe[H_DIM * 8];          // 4 KB
    __shared__ float4 sWr[H_DIM * 8];          // 4 KB

    int tid  = threadIdx.x;
    int tx   = tid & 7;
    int ty   = tid >> 3;
    int row0 = blockIdx.x * TILE_R;
    int rb   = ty * 4;

    sw0[tid]       = ((const float4*)lin0_w)[tid];
    sw0[tid + 256] = ((const float4*)lin0_w)[tid + 256];
    sWe[tid]       = ((const float4*)g_We)[tid];
    sWr[tid]       = ((const float4*)conv_root)[tid];
    float4 b0 = __ldg((const float4*)lin0_b + tx);
    float4 bc = __ldg((const float4*)conv_bias + tx);

    // stage x tile transposed: 128 rows x 16 float4 = 2048 f4, 8 per thread
    #pragma unroll
    for (int it = 0; it < 8; it++) {
        int m = tid + 256 * it;
        int r = m >> 4, q = m & 15;
        float4 v = make_float4(0.f, 0.f, 0.f, 0.f);
        if (row0 + r < n_nodes)
            v = __ldg((const float4*)(x + (size_t)(row0 + r) * IN_FEAT) + q);
        pool[swz(4 * q + 0, r)] = v.x;
        pool[swz(4 * q + 1, r)] = v.y;
        pool[swz(4 * q + 2, r)] = v.z;
        pool[swz(4 * q + 3, r)] = v.w;
    }
    __syncthreads();

    // ---- stage 1: h micro-tile (4 rows x 4 cols) ----
    float4 a0 = b0, a1 = b0, a2 = b0, a3 = b0;
    #pragma unroll 8
    for (int k = 0; k < IN_FEAT; k++) {
        float4 xv = *(const float4*)&pool[swz(k, rb)];
        float4 wv = sw0[k * 8 + tx];
        a0.x = fmaf(xv.x, wv.x, a0.x); a0.y = fmaf(xv.x, wv.y, a0.y);
        a0.z = fmaf(xv.x, wv.z, a0.z); a0.w = fmaf(xv.x, wv.w, a0.w);
        a1.x = fmaf(xv.y, wv.x, a1.x); a1.y = fmaf(xv.y, wv.y, a1.y);
        a1.z = fmaf(xv.y, wv.z, a1.z); a1.w = fmaf(xv.y, wv.w, a1.w);
        a2.x = fmaf(xv.z, wv.x, a2.x); a2.y = fmaf(xv.z, wv.y, a2.y);
        a2.z = fmaf(xv.z, wv.z, a2.z); a2.w = fmaf(xv.z, wv.w, a2.w);
        a3.x = fmaf(xv.w, wv.x, a3.x); a3.y = fmaf(xv.w, wv.y, a3.y);
        a3.z = fmaf(xv.w, wv.z, a3.z); a3.w = fmaf(xv.w, wv.w, a3.w);
    }
    __syncthreads();  // all xT reads complete before pool is reused

    {
        float4 rr[4] = {a0, a1, a2, a3};
        #pragma unroll
        for (int j = 0; j < 4; j++) {
            int r = rb + j;
            pool[swz(4 * tx + 0, r)] = relu(rr[j].x);
            pool[swz(4 * tx + 1, r)] = relu(rr[j].y);
            pool[swz(4 * tx + 2, r)] = relu(rr[j].z);
            pool[swz(4 * tx + 3, r)] = relu(rr[j].w);
        }
    }
    __syncthreads();

    // ---- stage 2: hWe = h@We (no bias), out = h@Wr + conv_bias ----
    float4 e0 = make_float4(0.f, 0.f, 0.f, 0.f), e1 = e0, e2 = e0, e3 = e0;
    float4 o0 = bc, o1 = bc, o2 = bc, o3 = bc;
    #pragma unroll 8
    for (int k = 0; k < H_DIM; k++) {
        float4 hv = *(const float4*)&pool[swz(k, rb)];
        float4 we = sWe[k * 8 + tx];
        float4 wr = sWr[k * 8 + tx];
        e0.x = fmaf(hv.x, we.x, e0.x); e0.y = fmaf(hv.x, we.y, e0.y);
        e0.z = fmaf(hv.x, we.z, e0.z); e0.w = fmaf(hv.x, we.w, e0.w);
        e1.x = fmaf(hv.y, we.x, e1.x); e1.y = fmaf(hv.y, we.y, e1.y);
        e1.z = fmaf(hv.y, we.z, e1.z); e1.w = fmaf(hv.y, we.w, e1.w);
        e2.x = fmaf(hv.z, we.x, e2.x); e2.y = fmaf(hv.z, we.y, e2.y);
        e2.z = fmaf(hv.z, we.z, e2.z); e2.w = fmaf(hv.z, we.w, e2.w);
        e3.x = fmaf(hv.w, we.x, e3.x); e3.y = fmaf(hv.w, we.y, e3.y);
        e3.z = fmaf(hv.w, we.z, e3.z); e3.w = fmaf(hv.w, we.w, e3.w);
        o0.x = fmaf(hv.x, wr.x, o0.x); o0.y = fmaf(hv.x, wr.y, o0.y);
        o0.z = fmaf(hv.x, wr.z, o0.z); o0.w = fmaf(hv.x, wr.w, o0.w);
        o1.x = fmaf(hv.y, wr.x, o1.x); o1.y = fmaf(hv.y, wr.y, o1.y);
        o1.z = fmaf(hv.y, wr.z, o1.z); o1.w = fmaf(hv.y, wr.w, o1.w);
        o2.x = fmaf(hv.z, wr.x, o2.x); o2.y = fmaf(hv.z, wr.y, o2.y);
        o2.z = fmaf(hv.z, wr.z, o2.z); o2.w = fmaf(hv.z, wr.w, o2.w);
        o3.x = fmaf(hv.w, wr.x, o3.x); o3.y = fmaf(hv.w, wr.y, o3.y);
        o3.z = fmaf(hv.w, wr.z, o3.z); o3.w = fmaf(hv.w, wr.w, o3.w);
    }

    float4 eres[4] = {e0, e1, e2, e3};
    float4 ores[4] = {o0, o1, o2, o3};
    #pragma unroll
    for (int i = 0; i < 4; i++) {
        int gr = row0 + rb + i;
        if (gr < n_nodes) {
            *(float4*)(g_hWe + (size_t)gr * H_DIM + tx * 4) = eres[i];
            *(float4*)(g_out + (size_t)gr * H_DIM + tx * 4) = ores[i];
        }
    }
}

// ============================================================
// K2: out[dst] += hWe[src]  — vector atomics. 8 threads per edge, each
// handles one float4 quarter via red.global.v4.f32.add.
// ============================================================
__global__ void k2_scatter(const int* __restrict__ edge_index, int n_edges) {
    long long tid = (long long)blockIdx.x * blockDim.x + threadIdx.x;
    int e = (int)(tid >> 3);
    if (e >= n_edges) return;
    int q = (int)(tid & 7);

    int src = __ldg(&edge_index[e]);            // edge_index[0][e]
    int dst = __ldg(&edge_index[n_edges + e]);  // edge_index[1][e]

    float4 v = __ldg((const float4*)(g_hWe + (size_t)src * H_DIM) + q);
    red_add_v4(g_out + (size_t)dst * H_DIM + q * 4, v);
}

// ============================================================
// K4: per-edge score, warp-autonomous two-phase.
// Each warp owns 32 edges and a private XOR-swizzled smem slice
// (32 edges x 32 floats = 1024 floats = 4 KB per warp, 32 KB total).
// Only __syncwarp between phases, so warps overlap freely.
// Phase A: lane i holds edge i's (src,dst); 8 passes x (shfl idx, 8-lane
//          coalesced row gathers, p = a*b, swizzled STS.128).
// Phase B: thread-per-edge; p read chunk-wise (swizzled LDS.128), weights
//          via broadcast LDS from block-shared sW1.
// Swizzle: addr = el*32 + 4*(q ^ (el&7)); conflict-free in both phases.
// ============================================================
__global__ void __launch_bounds__(256) k4_score(
        const int* __restrict__ edge_index,
        const float* __restrict__ lin1_w,
        const float* __restrict__ lin1_b,
        const float* __restrict__ lin2_w,
        const float* __restrict__ lin2_b,
        float* __restrict__ out_score,
        int n_edges) {
    __shared__ float pT[8][32 * H_DIM];       // 8 x 4 KB = 32 KB per-warp slices
    __shared__ float sW1[H_DIM * 8];          // row-major [k][j], 1 KB
    __shared__ float sB1[8], sW2[8];
    __shared__ float sB2;

    int tid  = threadIdx.x;
    int wid  = tid >> 5;
    int lane = tid & 31;

    if (tid < H_DIM * 8) sW1[tid] = lin1_w[tid];
    if (tid < 8) { sB1[tid] = lin1_b[tid]; sW2[tid] = lin2_w[tid]; }
    if (tid == 0) sB2 = lin2_b[0];
    __syncthreads();   // weights visible to all warps (once per block)

    const unsigned FULL = 0xFFFFFFFFu;
    int base = (blockIdx.x * 8 + wid) * 32;   // this warp's 32-edge tile
    int mye  = base + lane;
    int msrc = 0, mdst = 0;
    if (mye < n_edges) {
        msrc = __ldg(&edge_index[mye]);
        mdst = __ldg(&edge_index[n_edges + mye]);
    }

    float* P = &pT[wid][0];

    // Phase A: 8 passes; pass covers edges 4p..4p+3 (lane>>3 selects edge,
    // lane&7 selects float4 quarter -> 8-lane coalesced row gathers).
    #pragma unroll
    for (int ps = 0; ps < 8; ps++) {
        int el = ps * 4 + (lane >> 3);
        int q  = lane & 7;
        int s  = __shfl_sync(FULL, msrc, el);
        int d  = __shfl_sync(FULL, mdst, el);
        float4 a = __ldg((const float4*)(g_out + (size_t)s * H_DIM) + q);
        float4 b = __ldg((const float4*)(g_out + (size_t)d * H_DIM) + q);
        float4 pv = make_float4(a.x * b.x, a.y * b.y, a.z * b.z, a.w * b.w);
        *(float4*)&P[el * H_DIM + 4 * (q ^ (el & 7))] = pv;
    }
    __syncwarp();

    // Phase B: lane = edge (base+lane). p read 4-at-a-time from smem.
    float acc0 = sB1[0], acc1 = sB1[1], acc2 = sB1[2], acc3 = sB1[3];
    float acc4 = sB1[4], acc5 = sB1[5], acc6 = sB1[6], acc7 = sB1[7];
    #pragma unroll
    for (int q = 0; q < 8; q++) {
        float4 pv = *(const float4*)&P[lane * H_DIM + 4 * (q ^ (lane & 7))];
        int k = 4 * q;
        #pragma unroll
        for (int i = 0; i < 4; i++) {
            float pk = (i == 0) ? pv.x : (i == 1) ? pv.y : (i == 2) ? pv.z : pv.w;
            float4 w0 = *(const float4*)&sW1[(k + i) * 8];      // broadcast
            float4 w1 = *(const float4*)&sW1[(k + i) * 8 + 4];  // broadcast
            acc0 = fmaf(pk, w0.x, acc0); acc1 = fmaf(pk, w0.y, acc1);
            acc2 = fmaf(pk, w0.z, acc2); acc3 = fmaf(pk, w0.w, acc3);
            acc4 = fmaf(pk, w1.x, acc4); acc5 = fmaf(pk, w1.y, acc5);
            acc6 = fmaf(pk, w1.z, acc6); acc7 = fmaf(pk, w1.w, acc7);
        }
    }

    float score = sB2;
    score = fmaf(relu(acc0), sW2[0], score);
    score = fmaf(relu(acc1), sW2[1], score);
    score = fmaf(relu(acc2), sW2[2], score);
    score = fmaf(relu(acc3), sW2[3], score);
    score = fmaf(relu(acc4), sW2[4], score);
    score = fmaf(relu(acc5), sW2[5], score);
    score = fmaf(relu(acc6), sW2[6], score);
    score = fmaf(relu(acc7), sW2[7], score);

    if (mye < n_edges) out_score[mye] = score;   // coalesced STG.32
}

// ============================================================
// launch
// ============================================================
extern "C" void kernel_launch(void* const* d_in, const int* in_sizes, int n_in,
                              void* d_out, int out_size) {
    const float* x          = (const float*)d_in[0];
    const int*   edge_index = (const int*)d_in[1];   // int64 in JAX -> int32 in harness
    const float* lin0_w     = (const float*)d_in[2];
    const float* lin0_b     = (const float*)d_in[3];
    const float* nn_w1      = (const float*)d_in[4];
    const float* nn_b1      = (const float*)d_in[5];
    const float* nn_w2      = (const float*)d_in[6];
    const float* nn_b2      = (const float*)d_in[7];
    const float* conv_root  = (const float*)d_in[8];
    const float* conv_bias  = (const float*)d_in[9];
    const float* lin1_w     = (const float*)d_in[10];
    const float* lin1_b     = (const float*)d_in[11];
    const float* lin2_w     = (const float*)d_in[12];
    const float* lin2_b     = (const float*)d_in[13];
    float* out_score = (float*)d_out;

    int n_nodes = in_sizes[0] / IN_FEAT;
    int n_edges = in_sizes[1] / 2;

    // K0: shared edge weight matrix (tiny)
    k0_edge_weight<<<1, 256>>>(nn_w1, nn_b1, nn_w2, nn_b2);

    // K1 fused: h (smem-only) -> g_hWe and g_out init
    {
        int blocks = (n_nodes + TILE_R - 1) / TILE_R;
        k1_fused<<<blocks, 256>>>(x, lin0_w, lin0_b, conv_root, conv_bias,
                                  n_nodes);
    }

    // K2: 8 threads per edge, float4 reductions into g_out
    {
        long long total = (long long)n_edges * 8;
        int blocks = (int)((total + 255) / 256);
        k2_scatter<<<blocks, 256>>>(edge_index, n_edges);
    }

    // K4: warp-autonomous, 32 edges per warp (8 warps per block)
    {
        int warps = (n_edges + 31) / 32;
        int blocks = (warps + 7) / 8;
        k4_score<<<blocks, 256>>>(edge_index, lin1_w, lin1_b, lin2_w, lin2_b,
                                  out_score, n_edges);
    }
}